// round 1
// baseline (speedup 1.0000x reference)
#include <cuda_runtime.h>
#include <math.h>

// Problem constants
#define BB 2
#define SS 2048
#define DD 1024
#define HH 16
#define HDIM 64
#define SCALE 0.125f   // 64^-0.5

// Scratch (allocation-free rule: __device__ globals)
__device__ __align__(256) float g_Q[BB*SS*DD];
__device__ __align__(256) float g_K[BB*SS*DD];
__device__ __align__(256) float g_V[BB*SS*DD];
__device__ __align__(256) float g_C[BB*SS*DD];

// ---------------------------------------------------------------------------
// Projection GEMM: Out[m, h*64+e] = sum_d X[m,d] * W[h,d,e] + bias[h*64+e]
// Grid: (M/64, H). Block: 256 threads, 64x64 tile, BK=16, 4x4 per thread.
// sel: 0 -> g_Q, 1 -> g_K, 2 -> g_V
// ---------------------------------------------------------------------------
__global__ __launch_bounds__(256) void proj_kernel(
    const float* __restrict__ X, const float* __restrict__ W,
    const float* __restrict__ bias, int sel)
{
    float* Out = (sel == 0) ? g_Q : (sel == 1) ? g_K : g_V;
    __shared__ float As[16][65];
    __shared__ float Bs[16][65];

    const int h  = blockIdx.y;
    const int m0 = blockIdx.x * 64;
    const int tid = threadIdx.x;
    const int tx = tid & 15, ty = tid >> 4;
    const float* Wh = W + h * DD * HDIM;

    float acc[4][4] = {};

    for (int k0 = 0; k0 < DD; k0 += 16) {
        // A tile (64x16), float4 per thread, stored transposed
        {
            int m  = tid >> 2;
            int kq = (tid & 3) * 4;
            float4 v = *reinterpret_cast<const float4*>(X + (size_t)(m0 + m) * DD + k0 + kq);
            As[kq + 0][m] = v.x; As[kq + 1][m] = v.y;
            As[kq + 2][m] = v.z; As[kq + 3][m] = v.w;
        }
        // B tile (16x64) from W[h, k0+k, e] — contiguous in e
        #pragma unroll
        for (int l = 0; l < 4; l++) {
            int idx = tid + l * 256;
            int k = idx >> 6, e = idx & 63;
            Bs[k][e] = Wh[(size_t)(k0 + k) * HDIM + e];
        }
        __syncthreads();
        #pragma unroll
        for (int kk = 0; kk < 16; kk++) {
            float a[4], b[4];
            #pragma unroll
            for (int i = 0; i < 4; i++) a[i] = As[kk][ty * 4 + i];
            #pragma unroll
            for (int j = 0; j < 4; j++) b[j] = Bs[kk][tx * 4 + j];
            #pragma unroll
            for (int i = 0; i < 4; i++)
                #pragma unroll
                for (int j = 0; j < 4; j++)
                    acc[i][j] += a[i] * b[j];
        }
        __syncthreads();
    }

    #pragma unroll
    for (int i = 0; i < 4; i++) {
        int m = m0 + ty * 4 + i;
        #pragma unroll
        for (int j = 0; j < 4; j++) {
            int e = tx * 4 + j;
            Out[(size_t)m * DD + h * HDIM + e] = acc[i][j] + bias[h * HDIM + e];
        }
    }
}

// ---------------------------------------------------------------------------
// Flash attention, fp32. Grid: (S/64, H, B). Block 256. Q tile = 64 rows.
// Online softmax over 32 K-tiles of 64 rows.
// Dyn smem: Qs, Ks, Vs, Ps each 64x65 floats = 66560 B total.
// ---------------------------------------------------------------------------
#define LDP 65
__global__ __launch_bounds__(256) void attn_kernel()
{
    extern __shared__ float sm[];
    float* Qs = sm;
    float* Ks = sm + 64 * LDP;
    float* Vs = sm + 2 * 64 * LDP;
    float* Ps = sm + 3 * 64 * LDP;

    const int q0 = blockIdx.x * 64;
    const int h  = blockIdx.y;
    const int b  = blockIdx.z;
    const int tid = threadIdx.x;
    const int tx = tid & 15, ty = tid >> 4;

    const float* Qg = g_Q + (size_t)b * SS * DD + h * HDIM;
    const float* Kg = g_K + (size_t)b * SS * DD + h * HDIM;
    const float* Vg = g_V + (size_t)b * SS * DD + h * HDIM;

    // Load Q tile (64 rows x 64 cols), coalesced in e
    #pragma unroll
    for (int l = 0; l < 16; l++) {
        int idx = tid + l * 256;
        int r = idx >> 6, e = idx & 63;
        Qs[r * LDP + e] = Qg[(size_t)(q0 + r) * DD + e];
    }

    float O[4][4] = {};
    float mrow[4], lrow[4];
    #pragma unroll
    for (int i = 0; i < 4; i++) { mrow[i] = -INFINITY; lrow[i] = 0.f; }

    for (int kt = 0; kt < SS / 64; kt++) {
        const int kbase = kt * 64;
        __syncthreads();   // previous iter's readers of Ks/Vs done
        #pragma unroll
        for (int l = 0; l < 16; l++) {
            int idx = tid + l * 256;
            int r = idx >> 6, e = idx & 63;
            Ks[r * LDP + e] = Kg[(size_t)(kbase + r) * DD + e];
            Vs[r * LDP + e] = Vg[(size_t)(kbase + r) * DD + e];
        }
        __syncthreads();

        // S = Q @ K^T  (64x64), 4x4 per thread
        float s[4][4] = {};
        #pragma unroll 8
        for (int kk = 0; kk < 64; kk++) {
            float a[4], kv[4];
            #pragma unroll
            for (int i = 0; i < 4; i++) a[i]  = Qs[(ty * 4 + i) * LDP + kk];
            #pragma unroll
            for (int j = 0; j < 4; j++) kv[j] = Ks[(tx * 4 + j) * LDP + kk];
            #pragma unroll
            for (int i = 0; i < 4; i++)
                #pragma unroll
                for (int j = 0; j < 4; j++)
                    s[i][j] += a[i] * kv[j];
        }

        // Online softmax update; write P to smem
        #pragma unroll
        for (int i = 0; i < 4; i++) {
            float mx = -INFINITY;
            #pragma unroll
            for (int j = 0; j < 4; j++) {
                s[i][j] *= SCALE;
                mx = fmaxf(mx, s[i][j]);
            }
            #pragma unroll
            for (int off = 8; off > 0; off >>= 1)
                mx = fmaxf(mx, __shfl_xor_sync(0xffffffffu, mx, off, 16));
            float mnew  = fmaxf(mrow[i], mx);
            float alpha = __expf(mrow[i] - mnew);
            mrow[i] = mnew;
            float p[4], ls = 0.f;
            #pragma unroll
            for (int j = 0; j < 4; j++) { p[j] = __expf(s[i][j] - mnew); ls += p[j]; }
            #pragma unroll
            for (int off = 8; off > 0; off >>= 1)
                ls += __shfl_xor_sync(0xffffffffu, ls, off, 16);
            lrow[i] = lrow[i] * alpha + ls;
            #pragma unroll
            for (int j = 0; j < 4; j++) {
                O[i][j] *= alpha;
                Ps[(ty * 4 + i) * LDP + tx * 4 + j] = p[j];
            }
        }
        __syncthreads();

        // O += P @ V  (64x64 @ 64x64)
        #pragma unroll 8
        for (int kk = 0; kk < 64; kk++) {
            float a[4], vv[4];
            #pragma unroll
            for (int i = 0; i < 4; i++) a[i]  = Ps[(ty * 4 + i) * LDP + kk];
            #pragma unroll
            for (int j = 0; j < 4; j++) vv[j] = Vs[kk * LDP + tx * 4 + j];
            #pragma unroll
            for (int i = 0; i < 4; i++)
                #pragma unroll
                for (int j = 0; j < 4; j++)
                    O[i][j] += a[i] * vv[j];
        }
    }

    // Epilogue: normalize, write into concat layout [b, s, h*64+e]
    float* Og = g_C + (size_t)b * SS * DD + h * HDIM;
    #pragma unroll
    for (int i = 0; i < 4; i++) {
        float inv = 1.f / lrow[i];
        #pragma unroll
        for (int j = 0; j < 4; j++)
            Og[(size_t)(q0 + ty * 4 + i) * DD + tx * 4 + j] = O[i][j] * inv;
    }
}

// ---------------------------------------------------------------------------
// Output projection: Out[m,n] = sum_d C[m,d] * Wp[n,d] + bp[n]
// Grid: (M/64, D/64). Same tiling as proj.
// ---------------------------------------------------------------------------
__global__ __launch_bounds__(256) void outproj_kernel(
    const float* __restrict__ Wp, const float* __restrict__ bp,
    float* __restrict__ Out)
{
    __shared__ float As[16][65];
    __shared__ float Bs[16][65];

    const int n0 = blockIdx.y * 64;
    const int m0 = blockIdx.x * 64;
    const int tid = threadIdx.x;
    const int tx = tid & 15, ty = tid >> 4;

    float acc[4][4] = {};

    for (int k0 = 0; k0 < DD; k0 += 16) {
        {
            int m  = tid >> 2;
            int kq = (tid & 3) * 4;
            float4 v = *reinterpret_cast<const float4*>(g_C + (size_t)(m0 + m) * DD + k0 + kq);
            As[kq + 0][m] = v.x; As[kq + 1][m] = v.y;
            As[kq + 2][m] = v.z; As[kq + 3][m] = v.w;
        }
        {
            int n  = tid >> 2;
            int kq = (tid & 3) * 4;
            float4 v = *reinterpret_cast<const float4*>(Wp + (size_t)(n0 + n) * DD + k0 + kq);
            Bs[kq + 0][n] = v.x; Bs[kq + 1][n] = v.y;
            Bs[kq + 2][n] = v.z; Bs[kq + 3][n] = v.w;
        }
        __syncthreads();
        #pragma unroll
        for (int kk = 0; kk < 16; kk++) {
            float a[4], b[4];
            #pragma unroll
            for (int i = 0; i < 4; i++) a[i] = As[kk][ty * 4 + i];
            #pragma unroll
            for (int j = 0; j < 4; j++) b[j] = Bs[kk][tx * 4 + j];
            #pragma unroll
            for (int i = 0; i < 4; i++)
                #pragma unroll
                for (int j = 0; j < 4; j++)
                    acc[i][j] += a[i] * b[j];
        }
        __syncthreads();
    }

    #pragma unroll
    for (int i = 0; i < 4; i++) {
        int m = m0 + ty * 4 + i;
        #pragma unroll
        for (int j = 0; j < 4; j++) {
            int n = n0 + tx * 4 + j;
            Out[(size_t)m * DD + n] = acc[i][j] + bp[n];
        }
    }
}

// ---------------------------------------------------------------------------
// Launch
// Inputs (metadata order): K_in, V_in, Q_in, Wk, bk, Wq, bq, Wv, bv, Wp, bp
// ---------------------------------------------------------------------------
extern "C" void kernel_launch(void* const* d_in, const int* in_sizes, int n_in,
                              void* d_out, int out_size)
{
    const float* K_in = (const float*)d_in[0];
    const float* V_in = (const float*)d_in[1];
    const float* Q_in = (const float*)d_in[2];
    const float* Wk   = (const float*)d_in[3];
    const float* bk   = (const float*)d_in[4];
    const float* Wq   = (const float*)d_in[5];
    const float* bq   = (const float*)d_in[6];
    const float* Wv   = (const float*)d_in[7];
    const float* bv   = (const float*)d_in[8];
    const float* Wp   = (const float*)d_in[9];
    const float* bp   = (const float*)d_in[10];
    float* Out = (float*)d_out;

    const int M = BB * SS;                  // 4096
    dim3 blk(256);

    // Projections: Q, K, V
    proj_kernel<<<dim3(M / 64, HH), blk>>>(Q_in, Wq, bq, 0);
    proj_kernel<<<dim3(M / 64, HH), blk>>>(K_in, Wk, bk, 1);
    proj_kernel<<<dim3(M / 64, HH), blk>>>(V_in, Wv, bv, 2);

    // Flash attention
    const int smem = 4 * 64 * LDP * sizeof(float);   // 66560 B
    static int attr_set = 0;
    if (!attr_set) {
        cudaFuncSetAttribute(attn_kernel, cudaFuncAttributeMaxDynamicSharedMemorySize, smem);
        attr_set = 1;
    }
    attn_kernel<<<dim3(SS / 64, HH, BB), blk, smem>>>();

    // Output projection
    outproj_kernel<<<dim3(M / 64, DD / 64), blk>>>(Wp, bp, Out);
}

// round 2
// speedup vs baseline: 2.7108x; 2.7108x over previous
#include <cuda_runtime.h>
#include <cuda_bf16.h>
#include <math.h>
#include <stdint.h>

#define BB 2
#define SS 2048
#define DD 1024
#define HH 16
#define HDIM 64
#define SCALE 0.125f
#define MTOT (BB*SS)

typedef __nv_bfloat16 bf16;

// ---------------- device scratch (allocation-free rule) ----------------
__device__ __align__(256) bf16 g_xh[3][MTOT*DD];        // inputs hi (0=Q_in,1=K_in,2=V_in)
__device__ __align__(256) bf16 g_xl[3][MTOT*DD];
__device__ __align__(256) bf16 g_wh[3][HH*DD*HDIM];     // weights hi (0=Wq,1=Wk,2=Wv)
__device__ __align__(256) bf16 g_wl[3][HH*DD*HDIM];
__device__ __align__(256) bf16 g_wph[DD*DD];
__device__ __align__(256) bf16 g_wpl[DD*DD];
__device__ __align__(256) bf16 g_Qh[BB*HH*SS*HDIM];     // [b,h,s,e], pre-scaled by SCALE
__device__ __align__(256) bf16 g_Ql[BB*HH*SS*HDIM];
__device__ __align__(256) bf16 g_Kh[BB*HH*SS*HDIM];     // [b,h,s,e]
__device__ __align__(256) bf16 g_Kl[BB*HH*SS*HDIM];
__device__ __align__(256) bf16 g_Vh[BB*HH*HDIM*SS];     // [b,h,e,s]  (transposed)
__device__ __align__(256) bf16 g_Vl[BB*HH*HDIM*SS];
__device__ __align__(256) bf16 g_Ch[MTOT*DD];           // attention concat output
__device__ __align__(256) bf16 g_Cl[MTOT*DD];

// ---------------- helpers ----------------
__device__ __forceinline__ uint32_t packbf(float lo, float hi){
    uint32_t r; asm("cvt.rn.bf16x2.f32 %0, %1, %2;" : "=r"(r) : "f"(hi), "f"(lo)); return r;
}
__device__ __forceinline__ void splitf(float x, float& h, float& l){
    bf16 b = __float2bfloat16(x);
    h = __bfloat162float(b);
    l = x - h;
}
__device__ __forceinline__ void ldsm4(uint32_t* r, uint32_t a){
    asm volatile("ldmatrix.sync.aligned.m8n8.x4.shared.b16 {%0,%1,%2,%3}, [%4];"
        : "=r"(r[0]),"=r"(r[1]),"=r"(r[2]),"=r"(r[3]) : "r"(a));
}
__device__ __forceinline__ void ldsm4t(uint32_t* r, uint32_t a){
    asm volatile("ldmatrix.sync.aligned.m8n8.x4.trans.shared.b16 {%0,%1,%2,%3}, [%4];"
        : "=r"(r[0]),"=r"(r[1]),"=r"(r[2]),"=r"(r[3]) : "r"(a));
}
__device__ __forceinline__ void mma16816(float* c, const uint32_t* a, uint32_t b0, uint32_t b1){
    asm volatile("mma.sync.aligned.m16n8k16.row.col.f32.bf16.bf16.f32 "
        "{%0,%1,%2,%3}, {%4,%5,%6,%7}, {%8,%9}, {%0,%1,%2,%3};"
        : "+f"(c[0]),"+f"(c[1]),"+f"(c[2]),"+f"(c[3])
        : "r"(a[0]),"r"(a[1]),"r"(a[2]),"r"(a[3]), "r"(b0),"r"(b1));
}

// ---------------- split fp32 -> (bf16 hi, bf16 lo) ----------------
__global__ void split_kernel(const float* __restrict__ x, int dst, int n2){
    int i = blockIdx.x*blockDim.x + threadIdx.x;
    if (i >= n2) return;
    float2 v = reinterpret_cast<const float2*>(x)[i];
    float h0,l0,h1,l1; splitf(v.x,h0,l0); splitf(v.y,h1,l1);
    uint32_t *ph, *pl;
    if (dst < 3)      { ph = (uint32_t*)g_xh[dst];   pl = (uint32_t*)g_xl[dst]; }
    else if (dst < 6) { ph = (uint32_t*)g_wh[dst-3]; pl = (uint32_t*)g_wl[dst-3]; }
    else              { ph = (uint32_t*)g_wph;       pl = (uint32_t*)g_wpl; }
    ph[i] = packbf(h0,h1);
    pl[i] = packbf(l0,l1);
}

// ---------------- projection GEMM (Q/K/V) ----------------
// Out[m, h, e] = sum_d X[m,d] * W[h,d,e] + bias[h,e]   (bf16x3 via mma)
// Grid (32, 16, 3). Block 256. CTA tile 128(m) x 64(e), BK=64.
__global__ __launch_bounds__(256) void proj_mma(
    const float* __restrict__ bq, const float* __restrict__ bk, const float* __restrict__ bv)
{
    extern __shared__ bf16 smem[];
    bf16* As_h = smem;               // [128][72] (m, k)
    bf16* As_l = As_h + 128*72;
    bf16* Bs_h = As_l + 128*72;      // [64][72]  (k, n)  -> ldmatrix.trans for B frags
    bf16* Bs_l = Bs_h + 64*72;

    const int sel = blockIdx.z;
    const int hid = blockIdx.y;
    const int m0  = blockIdx.x * 128;
    const int tid = threadIdx.x;
    const int lane = tid & 31, warp = tid >> 5;
    const int wm = warp * 16;

    const uint32_t* Xh32 = (const uint32_t*)(g_xh[sel] + (size_t)m0 * DD);
    const uint32_t* Xl32 = (const uint32_t*)(g_xl[sel] + (size_t)m0 * DD);
    const uint32_t* Wh32 = (const uint32_t*)(g_wh[sel] + (size_t)hid * DD * HDIM);
    const uint32_t* Wl32 = (const uint32_t*)(g_wl[sel] + (size_t)hid * DD * HDIM);
    const float* bias = (sel == 0) ? bq : (sel == 1) ? bk : bv;
    const float scale = (sel == 0) ? SCALE : 1.0f;

    uint32_t* dAh = (uint32_t*)As_h; uint32_t* dAl = (uint32_t*)As_l;
    uint32_t* dBh = (uint32_t*)Bs_h; uint32_t* dBl = (uint32_t*)Bs_l;
    uint32_t aAh = (uint32_t)__cvta_generic_to_shared(As_h);
    uint32_t aAl = (uint32_t)__cvta_generic_to_shared(As_l);
    uint32_t aBh = (uint32_t)__cvta_generic_to_shared(Bs_h);
    uint32_t aBl = (uint32_t)__cvta_generic_to_shared(Bs_l);

    // A frag addresses: rows wm..wm+15, k-tile offset per kk
    const uint32_t a_off  = (uint32_t)((wm + (lane & 15))*72 + (lane >> 4)*8) * 2;
    // trans-B frag addresses over [k][n] tiles
    const uint32_t bt_off = (uint32_t)((((lane >> 3) & 1)*8 + (lane & 7))*72 + (lane >> 4)*8) * 2;

    float acc[8][4] = {};

    for (int k0 = 0; k0 < DD; k0 += 64){
        __syncthreads();
        #pragma unroll
        for (int i = 0; i < 16; i++){
            int idx = tid + i*256, r = idx >> 5, c = idx & 31;
            dAh[r*36+c] = Xh32[r*512 + (k0>>1) + c];
            dAl[r*36+c] = Xl32[r*512 + (k0>>1) + c];
        }
        #pragma unroll
        for (int i = 0; i < 8; i++){
            int idx = tid + i*256, r = idx >> 5, c = idx & 31;
            dBh[r*36+c] = Wh32[(k0 + r)*32 + c];
            dBl[r*36+c] = Wl32[(k0 + r)*32 + c];
        }
        __syncthreads();
        #pragma unroll
        for (int kk = 0; kk < 4; kk++){
            uint32_t ah[4], al[4];
            ldsm4(ah, aAh + a_off + kk*32);
            ldsm4(al, aAl + a_off + kk*32);
            #pragma unroll
            for (int np = 0; np < 4; np++){
                uint32_t bh[4], bl[4];
                uint32_t off = bt_off + (uint32_t)(kk*16*72 + np*16)*2;
                ldsm4t(bh, aBh + off);
                ldsm4t(bl, aBl + off);
                mma16816(acc[2*np],   ah, bh[0], bh[1]);
                mma16816(acc[2*np],   ah, bl[0], bl[1]);
                mma16816(acc[2*np],   al, bh[0], bh[1]);
                mma16816(acc[2*np+1], ah, bh[2], bh[3]);
                mma16816(acc[2*np+1], ah, bl[2], bl[3]);
                mma16816(acc[2*np+1], al, bh[2], bh[3]);
            }
        }
    }

    // epilogue: add bias, apply scale (Q only), split -> hi/lo bf16
    bf16* oh = (sel==0) ? g_Qh : (sel==1) ? g_Kh : g_Vh;
    bf16* ol = (sel==0) ? g_Ql : (sel==1) ? g_Kl : g_Vl;
    const int r0 = m0 + wm + (lane >> 2);
    const int cb = 2*(lane & 3);
    #pragma unroll
    for (int nt = 0; nt < 8; nt++){
        int e = nt*8 + cb;
        float b0v = bias[hid*HDIM + e], b1v = bias[hid*HDIM + e + 1];
        float v[4];
        v[0] = (acc[nt][0] + b0v)*scale;
        v[1] = (acc[nt][1] + b1v)*scale;
        v[2] = (acc[nt][2] + b0v)*scale;
        v[3] = (acc[nt][3] + b1v)*scale;
        #pragma unroll
        for (int half = 0; half < 2; half++){
            int m = r0 + half*8;
            int bI = m >> 11, s = m & (SS-1);
            #pragma unroll
            for (int j = 0; j < 2; j++){
                float hh, llv; splitf(v[half*2 + j], hh, llv);
                size_t idx;
                if (sel == 2) idx = (((size_t)(bI*HH + hid))*HDIM + (e+j))*SS + s;
                else          idx = (((size_t)(bI*HH + hid))*SS + s)*HDIM + (e+j);
                oh[idx] = __float2bfloat16(hh);
                ol[idx] = __float2bfloat16(llv);
            }
        }
    }
}

// ---------------- flash attention (bf16x3 mma, fp32 softmax) ----------------
// Grid (16, 16, 2). Block 256 (8 warps, warp owns 16 q-rows). Q tile 128, K tile 64.
__global__ __launch_bounds__(256) void attn_mma()
{
    extern __shared__ bf16 smem[];
    bf16* Qs_h = smem;               // [128][72] (s, e)
    bf16* Qs_l = Qs_h + 128*72;
    bf16* Ks_h = Qs_l + 128*72;      // [64][72]  (s, e)
    bf16* Ks_l = Ks_h + 64*72;
    bf16* Vs_h = Ks_l + 64*72;       // [64][72]  (e, s)
    bf16* Vs_l = Vs_h + 64*72;

    const int q0 = blockIdx.x*128;
    const int hid = blockIdx.y, bI = blockIdx.z;
    const int bh = bI*HH + hid;
    const int tid = threadIdx.x, lane = tid & 31, warp = tid >> 5;
    const int wm = warp*16;

    const uint32_t* Qh32 = (const uint32_t*)(g_Qh + ((size_t)bh*SS + q0)*HDIM);
    const uint32_t* Ql32 = (const uint32_t*)(g_Ql + ((size_t)bh*SS + q0)*HDIM);
    const uint32_t* Kh32 = (const uint32_t*)(g_Kh + (size_t)bh*SS*HDIM);
    const uint32_t* Kl32 = (const uint32_t*)(g_Kl + (size_t)bh*SS*HDIM);
    const uint32_t* Vh32 = (const uint32_t*)(g_Vh + (size_t)bh*HDIM*SS);
    const uint32_t* Vl32 = (const uint32_t*)(g_Vl + (size_t)bh*HDIM*SS);

    uint32_t* dQh = (uint32_t*)Qs_h; uint32_t* dQl = (uint32_t*)Qs_l;
    uint32_t* dKh = (uint32_t*)Ks_h; uint32_t* dKl = (uint32_t*)Ks_l;
    uint32_t* dVh = (uint32_t*)Vs_h; uint32_t* dVl = (uint32_t*)Vs_l;

    #pragma unroll
    for (int i = 0; i < 16; i++){
        int idx = tid + i*256, r = idx >> 5, c = idx & 31;
        dQh[r*36+c] = Qh32[r*32+c];
        dQl[r*36+c] = Ql32[r*32+c];
    }

    uint32_t aQh = (uint32_t)__cvta_generic_to_shared(Qs_h);
    uint32_t aQl = (uint32_t)__cvta_generic_to_shared(Qs_l);
    uint32_t aKh = (uint32_t)__cvta_generic_to_shared(Ks_h);
    uint32_t aKl = (uint32_t)__cvta_generic_to_shared(Ks_l);
    uint32_t aVh = (uint32_t)__cvta_generic_to_shared(Vs_h);
    uint32_t aVl = (uint32_t)__cvta_generic_to_shared(Vs_l);

    const uint32_t a_off = (uint32_t)((wm + (lane & 15))*72 + (lane >> 4)*8) * 2;
    // no-trans B frag base ([n][k] rows)
    const uint32_t b_off = (uint32_t)(((lane >> 4)*8 + (lane & 7))*72 + ((lane >> 3) & 1)*8) * 2;

    float o[8][4] = {};
    float ml0 = -1e30f, ml1 = -1e30f, ll0 = 0.f, ll1 = 0.f;

    for (int kt = 0; kt < SS/64; kt++){
        const int kb = kt*64;
        __syncthreads();
        #pragma unroll
        for (int i = 0; i < 8; i++){
            int idx = tid + i*256, r = idx >> 5, c = idx & 31;
            dKh[r*36+c] = Kh32[(kb + r)*32 + c];
            dKl[r*36+c] = Kl32[(kb + r)*32 + c];
            dVh[r*36+c] = Vh32[r*1024 + (kb>>1) + c];
            dVl[r*36+c] = Vl32[r*1024 + (kb>>1) + c];
        }
        __syncthreads();

        // S = Q K^T (pre-scaled Q)
        float s[8][4] = {};
        #pragma unroll
        for (int kk = 0; kk < 4; kk++){
            uint32_t qh[4], ql[4];
            ldsm4(qh, aQh + a_off + kk*32);
            ldsm4(ql, aQl + a_off + kk*32);
            #pragma unroll
            for (int np = 0; np < 4; np++){
                uint32_t kh[4], kl[4];
                uint32_t off = b_off + (uint32_t)(np*16*72 + kk*16)*2;
                ldsm4(kh, aKh + off);
                ldsm4(kl, aKl + off);
                mma16816(s[2*np],   qh, kh[0], kh[1]);
                mma16816(s[2*np],   qh, kl[0], kl[1]);
                mma16816(s[2*np],   ql, kh[0], kh[1]);
                mma16816(s[2*np+1], qh, kh[2], kh[3]);
                mma16816(s[2*np+1], qh, kl[2], kl[3]);
                mma16816(s[2*np+1], ql, kh[2], kh[3]);
            }
        }

        // online softmax (rows r=lane/4 and r+8, replicated across 4-lane groups)
        float mx0 = -1e30f, mx1 = -1e30f;
        #pragma unroll
        for (int nt = 0; nt < 8; nt++){
            mx0 = fmaxf(mx0, fmaxf(s[nt][0], s[nt][1]));
            mx1 = fmaxf(mx1, fmaxf(s[nt][2], s[nt][3]));
        }
        mx0 = fmaxf(mx0, __shfl_xor_sync(0xffffffffu, mx0, 1));
        mx0 = fmaxf(mx0, __shfl_xor_sync(0xffffffffu, mx0, 2));
        mx1 = fmaxf(mx1, __shfl_xor_sync(0xffffffffu, mx1, 1));
        mx1 = fmaxf(mx1, __shfl_xor_sync(0xffffffffu, mx1, 2));
        float mn0 = fmaxf(ml0, mx0), mn1 = fmaxf(ml1, mx1);
        float al0 = __expf(ml0 - mn0), al1 = __expf(ml1 - mn1);
        ml0 = mn0; ml1 = mn1;
        float ls0 = 0.f, ls1 = 0.f;
        #pragma unroll
        for (int nt = 0; nt < 8; nt++){
            s[nt][0] = __expf(s[nt][0] - mn0);
            s[nt][1] = __expf(s[nt][1] - mn0);
            s[nt][2] = __expf(s[nt][2] - mn1);
            s[nt][3] = __expf(s[nt][3] - mn1);
            ls0 += s[nt][0] + s[nt][1];
            ls1 += s[nt][2] + s[nt][3];
        }
        ls0 += __shfl_xor_sync(0xffffffffu, ls0, 1);
        ls0 += __shfl_xor_sync(0xffffffffu, ls0, 2);
        ls1 += __shfl_xor_sync(0xffffffffu, ls1, 1);
        ls1 += __shfl_xor_sync(0xffffffffu, ls1, 2);
        ll0 = ll0*al0 + ls0;
        ll1 = ll1*al1 + ls1;
        #pragma unroll
        for (int nt = 0; nt < 8; nt++){
            o[nt][0] *= al0; o[nt][1] *= al0;
            o[nt][2] *= al1; o[nt][3] *= al1;
        }

        // O += P V  (P repacked from S accumulators into A frags, split hi/lo)
        #pragma unroll
        for (int kk = 0; kk < 4; kk++){
            const int t0 = 2*kk, t1 = 2*kk + 1;
            uint32_t pah[4], pal[4];
            float h0,l0v,h1,l1v;
            splitf(s[t0][0],h0,l0v); splitf(s[t0][1],h1,l1v);
            pah[0] = packbf(h0,h1);  pal[0] = packbf(l0v,l1v);
            splitf(s[t0][2],h0,l0v); splitf(s[t0][3],h1,l1v);
            pah[1] = packbf(h0,h1);  pal[1] = packbf(l0v,l1v);
            splitf(s[t1][0],h0,l0v); splitf(s[t1][1],h1,l1v);
            pah[2] = packbf(h0,h1);  pal[2] = packbf(l0v,l1v);
            splitf(s[t1][2],h0,l0v); splitf(s[t1][3],h1,l1v);
            pah[3] = packbf(h0,h1);  pal[3] = packbf(l0v,l1v);
            #pragma unroll
            for (int np = 0; np < 4; np++){
                uint32_t vh[4], vl[4];
                uint32_t off = b_off + (uint32_t)(np*16*72 + kk*16)*2;
                ldsm4(vh, aVh + off);
                ldsm4(vl, aVl + off);
                mma16816(o[2*np],   pah, vh[0], vh[1]);
                mma16816(o[2*np],   pah, vl[0], vl[1]);
                mma16816(o[2*np],   pal, vh[0], vh[1]);
                mma16816(o[2*np+1], pah, vh[2], vh[3]);
                mma16816(o[2*np+1], pah, vl[2], vl[3]);
                mma16816(o[2*np+1], pal, vh[2], vh[3]);
            }
        }
    }

    // epilogue: normalize and write concat (hi/lo bf16)
    float inv0 = 1.f/ll0, inv1 = 1.f/ll1;
    const int sr = q0 + wm + (lane >> 2);
    const int cb = 2*(lane & 3);
    #pragma unroll
    for (int nt = 0; nt < 8; nt++){
        int e = hid*HDIM + nt*8 + cb;
        #pragma unroll
        for (int half = 0; half < 2; half++){
            int srow = sr + half*8;
            float inv = half ? inv1 : inv0;
            size_t base = ((size_t)(bI*SS + srow))*DD + e;
            #pragma unroll
            for (int j = 0; j < 2; j++){
                float hh, llv; splitf(o[nt][half*2 + j]*inv, hh, llv);
                g_Ch[base + j] = __float2bfloat16(hh);
                g_Cl[base + j] = __float2bfloat16(llv);
            }
        }
    }
}

// ---------------- output projection: Out = C @ Wp^T + bp ----------------
// Grid (32, 16). Block 256. CTA tile 128(m) x 64(n), BK=64.
__global__ __launch_bounds__(256) void outproj_mma(
    const float* __restrict__ bp, float* __restrict__ Out)
{
    extern __shared__ bf16 smem[];
    bf16* As_h = smem;               // [128][72] (m, k)
    bf16* As_l = As_h + 128*72;
    bf16* Bs_h = As_l + 128*72;      // [64][72]  (n, k)  -> no-trans B frags
    bf16* Bs_l = Bs_h + 64*72;

    const int m0 = blockIdx.x * 128;
    const int n0 = blockIdx.y * 64;
    const int tid = threadIdx.x;
    const int lane = tid & 31, warp = tid >> 5;
    const int wm = warp * 16;

    const uint32_t* Ah32 = (const uint32_t*)(g_Ch + (size_t)m0 * DD);
    const uint32_t* Al32 = (const uint32_t*)(g_Cl + (size_t)m0 * DD);
    const uint32_t* Wh32 = (const uint32_t*)g_wph;
    const uint32_t* Wl32 = (const uint32_t*)g_wpl;

    uint32_t* dAh = (uint32_t*)As_h; uint32_t* dAl = (uint32_t*)As_l;
    uint32_t* dBh = (uint32_t*)Bs_h; uint32_t* dBl = (uint32_t*)Bs_l;
    uint32_t aAh = (uint32_t)__cvta_generic_to_shared(As_h);
    uint32_t aAl = (uint32_t)__cvta_generic_to_shared(As_l);
    uint32_t aBh = (uint32_t)__cvta_generic_to_shared(Bs_h);
    uint32_t aBl = (uint32_t)__cvta_generic_to_shared(Bs_l);

    const uint32_t a_off = (uint32_t)((wm + (lane & 15))*72 + (lane >> 4)*8) * 2;
    const uint32_t b_off = (uint32_t)(((lane >> 4)*8 + (lane & 7))*72 + ((lane >> 3) & 1)*8) * 2;

    float acc[8][4] = {};

    for (int k0 = 0; k0 < DD; k0 += 64){
        __syncthreads();
        #pragma unroll
        for (int i = 0; i < 16; i++){
            int idx = tid + i*256, r = idx >> 5, c = idx & 31;
            dAh[r*36+c] = Ah32[r*512 + (k0>>1) + c];
            dAl[r*36+c] = Al32[r*512 + (k0>>1) + c];
        }
        #pragma unroll
        for (int i = 0; i < 8; i++){
            int idx = tid + i*256, r = idx >> 5, c = idx & 31;
            dBh[r*36+c] = Wh32[(size_t)(n0 + r)*512 + (k0>>1) + c];
            dBl[r*36+c] = Wl32[(size_t)(n0 + r)*512 + (k0>>1) + c];
        }
        __syncthreads();
        #pragma unroll
        for (int kk = 0; kk < 4; kk++){
            uint32_t ah[4], al[4];
            ldsm4(ah, aAh + a_off + kk*32);
            ldsm4(al, aAl + a_off + kk*32);
            #pragma unroll
            for (int np = 0; np < 4; np++){
                uint32_t bh[4], bl[4];
                uint32_t off = b_off + (uint32_t)(np*16*72 + kk*16)*2;
                ldsm4(bh, aBh + off);
                ldsm4(bl, aBl + off);
                mma16816(acc[2*np],   ah, bh[0], bh[1]);
                mma16816(acc[2*np],   ah, bl[0], bl[1]);
                mma16816(acc[2*np],   al, bh[0], bh[1]);
                mma16816(acc[2*np+1], ah, bh[2], bh[3]);
                mma16816(acc[2*np+1], ah, bl[2], bl[3]);
                mma16816(acc[2*np+1], al, bh[2], bh[3]);
            }
        }
    }

    const int r0 = m0 + wm + (lane >> 2);
    const int cb = 2*(lane & 3);
    #pragma unroll
    for (int nt = 0; nt < 8; nt++){
        int n = n0 + nt*8 + cb;
        float b0v = bp[n], b1v = bp[n+1];
        Out[(size_t)r0*DD + n]       = acc[nt][0] + b0v;
        Out[(size_t)r0*DD + n + 1]   = acc[nt][1] + b1v;
        Out[(size_t)(r0+8)*DD + n]   = acc[nt][2] + b0v;
        Out[(size_t)(r0+8)*DD + n+1] = acc[nt][3] + b1v;
    }
}

// ---------------- launch ----------------
// Inputs: K_in, V_in, Q_in, Wk, bk, Wq, bq, Wv, bv, Wp, bp
extern "C" void kernel_launch(void* const* d_in, const int* in_sizes, int n_in,
                              void* d_out, int out_size)
{
    const float* K_in = (const float*)d_in[0];
    const float* V_in = (const float*)d_in[1];
    const float* Q_in = (const float*)d_in[2];
    const float* Wk   = (const float*)d_in[3];
    const float* bk   = (const float*)d_in[4];
    const float* Wq   = (const float*)d_in[5];
    const float* bq   = (const float*)d_in[6];
    const float* Wv   = (const float*)d_in[7];
    const float* bv   = (const float*)d_in[8];
    const float* Wp   = (const float*)d_in[9];
    const float* bp   = (const float*)d_in[10];
    float* Out = (float*)d_out;

    const int n2x = MTOT*DD/2;        // 2M float2
    const int n2w = HH*DD*HDIM/2;     // 512K
    const int n2p = DD*DD/2;          // 512K

    split_kernel<<<(n2x+255)/256, 256>>>(Q_in, 0, n2x);
    split_kernel<<<(n2x+255)/256, 256>>>(K_in, 1, n2x);
    split_kernel<<<(n2x+255)/256, 256>>>(V_in, 2, n2x);
    split_kernel<<<(n2w+255)/256, 256>>>(Wq, 3, n2w);
    split_kernel<<<(n2w+255)/256, 256>>>(Wk, 4, n2w);
    split_kernel<<<(n2w+255)/256, 256>>>(Wv, 5, n2w);
    split_kernel<<<(n2p+255)/256, 256>>>(Wp, 6, n2p);

    static int init = 0;
    if (!init){
        cudaFuncSetAttribute(proj_mma,    cudaFuncAttributeMaxDynamicSharedMemorySize, 55296);
        cudaFuncSetAttribute(attn_mma,    cudaFuncAttributeMaxDynamicSharedMemorySize, 73728);
        cudaFuncSetAttribute(outproj_mma, cudaFuncAttributeMaxDynamicSharedMemorySize, 55296);
        init = 1;
    }

    proj_mma<<<dim3(MTOT/128, HH, 3), 256, 55296>>>(bq, bk, bv);
    attn_mma<<<dim3(SS/128, HH, BB), 256, 73728>>>();
    outproj_mma<<<dim3(MTOT/128, DD/64), 256, 55296>>>(bp, Out);
}